// round 14
// baseline (speedup 1.0000x reference)
#include <cuda_runtime.h>
#include <cuda_bf16.h>
#include <math.h>
#include <stdint.h>

// Problem constants
#define B_ 128
#define S_ 512
#define D_ 512
#define H_ 512
#define V_ 50000

// d_out layout: logits | hidden | cell | attn
#define OUT_HID  (B_ * V_)
#define OUT_CELL (OUT_HID + B_ * H_)
#define OUT_ATTN (OUT_CELL + B_ * H_)

// ---------------- device scratch ----------------
__device__ float g_wq[B_ * D_];
__device__ float g_ctx[B_ * D_];
__device__ float g_scores_p[4 * B_ * S_];
__device__ float g_gates_p[6 * B_ * 4 * H_];
__device__ uint32_t g_wcf[D_ * D_];        // W_ctx as tf32 bits
__device__ uint32_t g_gaf[B_ * 1536];      // concat(y_prev,ctx,h0) tf32 bits
__device__ uint32_t g_hf[B_ * H_];         // hidden tf32 bits

// ======================= helpers =======================
__device__ __forceinline__ uint32_t tf32b(float x) {
    uint32_t r;
    asm("cvt.rna.tf32.f32 %0, %1;" : "=r"(r) : "f"(x));
    return r;
}

__device__ __forceinline__ void mma_tf32(float* d, const uint32_t* a,
                                         uint32_t b0, uint32_t b1) {
    asm volatile("mma.sync.aligned.m16n8k8.row.col.f32.tf32.tf32.f32 "
        "{%0,%1,%2,%3},{%4,%5,%6,%7},{%8,%9},{%0,%1,%2,%3};"
        : "+f"(d[0]), "+f"(d[1]), "+f"(d[2]), "+f"(d[3])
        : "r"(a[0]), "r"(a[1]), "r"(a[2]), "r"(a[3]), "r"(b0), "r"(b1));
}

__device__ __forceinline__ float tanh_fast(float x) {
    float y;
    asm("tanh.approx.f32 %0, %1;" : "=f"(y) : "f"(x));
    return y;
}

// tf32 tile: 64 k-words + 4 pad = 68 words (272 B) per row, 128 rows
#define PAD_F 68
#define T_A   0
#define T_B   34816
#define T2_END 69632

__device__ __forceinline__ void cvt_store4(float4 v, char* base, int row, int f4) {
    uint4 u;
    u.x = tf32b(v.x); u.y = tf32b(v.y); u.z = tf32b(v.z); u.w = tf32b(v.w);
    *(uint4*)(base + row * (PAD_F * 4) + f4 * 16) = u;
}

// ---------------------------------------------------------------------------
// K0a/K0b: pre-convert W_ctx to tf32 (blocks 0-127) + one gates operand
// (blocks 128-191: launch 0 -> y_prev at col 0; launch 1 -> h0 at col 1024)
// ---------------------------------------------------------------------------
__global__ void wc_prep_kernel(const float* __restrict__ Wc, int base,
                               const float* __restrict__ extra, int coloff)
{
    if (blockIdx.x < 128) {
        const int i = base + blockIdx.x * 256 + threadIdx.x;
        float4 v = ((const float4*)Wc)[i];
        uint4 u;
        u.x = tf32b(v.x); u.y = tf32b(v.y); u.z = tf32b(v.z); u.w = tf32b(v.w);
        ((uint4*)g_wcf)[i] = u;
    } else {
        const int j = (blockIdx.x - 128) * 256 + threadIdx.x;  // 0..16383 f4s
        const int row = j >> 7, c4 = j & 127;
        float4 v = ((const float4*)(extra + (size_t)row * 512))[c4];
        uint4 u;
        u.x = tf32b(v.x); u.y = tf32b(v.y); u.z = tf32b(v.z); u.w = tf32b(v.w);
        *(uint4*)(g_gaf + (size_t)row * 1536 + coloff + c4 * 4) = u;
    }
}

// ---------------------------------------------------------------------------
// K1: wq = h0 @ W_q^T + b_q. grid 16 x 512 thr: block = 8 batch rows,
// thread = one d column. W_q read 16x total (vs 128x before).
// ---------------------------------------------------------------------------
__global__ __launch_bounds__(512)
void wq_kernel(const float* __restrict__ h0,
               const float* __restrict__ Wq,
               const float* __restrict__ bq)
{
    const int b0 = blockIdx.x * 8;
    const int tid = threadIdx.x;            // = d
    __shared__ float hs[8 * 512];
    for (int i = tid; i < 4096; i += 512) hs[i] = h0[b0 * 512 + i];
    __syncthreads();

    const float4* w = (const float4*)(Wq + (size_t)tid * 512);
    float acc[8];
#pragma unroll
    for (int bb = 0; bb < 8; ++bb) acc[bb] = 0.f;
#pragma unroll 4
    for (int k4 = 0; k4 < 128; ++k4) {
        const float4 wv = w[k4];
#pragma unroll
        for (int bb = 0; bb < 8; ++bb) {
            const float4 hv = ((const float4*)(hs + bb * 512))[k4];
            acc[bb] += wv.x * hv.x + wv.y * hv.y + wv.z * hv.z + wv.w * hv.w;
        }
    }
    const float bqd = bq[tid];
#pragma unroll
    for (int bb = 0; bb < 8; ++bb)
        g_wq[(size_t)(b0 + bb) * D_ + tid] = acc[bb] + bqd;
}

// ---------------------------------------------------------------------------
// K2 (TF32 MMA): fused attention-score GEMM. (round-13 best config)
// ---------------------------------------------------------------------------
#define AT_RED  T2_END                 // float[2][128]
#define AT_WQ   (AT_RED + 1024)
#define AT_V    (AT_WQ + 512)
#define AT_SZ   (AT_V + 512)           // 71680

__global__ __launch_bounds__(128, 2)
void attn_hmma_kernel(const float* __restrict__ enc,
                      const float* __restrict__ vw)
{
    extern __shared__ char smem[];
    const int tid = threadIdx.x;
    const int lane = tid & 31, warp = tid >> 5;
    const int wm = warp >> 1, wn = warp & 1;
    const int grp = lane >> 2, tg = lane & 3;
    const int ntile = blockIdx.x;
    const int m0 = blockIdx.y * 128;
    const int n0 = ntile * 128;
    const int b = m0 >> 9;

    float* wq_s = (float*)(smem + AT_WQ);
    float* v_s  = (float*)(smem + AT_V);
    wq_s[tid] = g_wq[b * D_ + n0 + tid];
    v_s[tid]  = vw[n0 + tid];

    float c[4][8][4];
#pragma unroll
    for (int i = 0; i < 4; ++i)
#pragma unroll
        for (int j = 0; j < 8; ++j)
#pragma unroll
            for (int e = 0; e < 4; ++e) c[i][j][e] = 0.f;

    const uint32_t* As = (const uint32_t*)(smem + T_A);
    const uint32_t* Bs = (const uint32_t*)(smem + T_B);
    const int ld_row = tid >> 4, ld_f4 = tid & 15;

    for (int chunk = 0; chunk < 8; ++chunk) {
        const int k0 = chunk * 64;
        __syncthreads();
#pragma unroll
        for (int i = 0; i < 16; ++i) {                // A: enc fp32 -> tf32
            const int row = ld_row + 8 * i;
            float4 v = *(const float4*)(enc + (size_t)(m0 + row) * D_ + k0 + ld_f4 * 4);
            cvt_store4(v, smem + T_A, row, ld_f4);
        }
#pragma unroll
        for (int i = 0; i < 16; ++i) {                // B: tf32 copy
            const int row = ld_row + 8 * i;
            uint4 u = *(const uint4*)(g_wcf + (size_t)(n0 + row) * D_ + k0 + ld_f4 * 4);
            *(uint4*)(smem + T_B + row * (PAD_F * 4) + ld_f4 * 16) = u;
        }
        __syncthreads();

#pragma unroll
        for (int ks = 0; ks < 8; ++ks) {
            uint32_t a[4][4];
#pragma unroll
            for (int mf = 0; mf < 4; ++mf) {
                const uint32_t* p = As + (wm * 64 + mf * 16 + grp) * PAD_F + ks * 8 + tg;
                a[mf][0] = p[0]; a[mf][1] = p[8 * PAD_F];
                a[mf][2] = p[4]; a[mf][3] = p[8 * PAD_F + 4];
            }
            uint32_t bf[8][2];
#pragma unroll
            for (int nf = 0; nf < 8; ++nf) {
                const uint32_t* q = Bs + (wn * 64 + nf * 8 + grp) * PAD_F + ks * 8 + tg;
                bf[nf][0] = q[0]; bf[nf][1] = q[4];
            }
#pragma unroll
            for (int mf = 0; mf < 4; ++mf)
#pragma unroll
                for (int nf = 0; nf < 8; ++nf)
                    mma_tf32(c[mf][nf], a[mf], bf[nf][0], bf[nf][1]);
        }
    }

    float* red = (float*)(smem + AT_RED);             // [2][128]
    __syncthreads();
#pragma unroll
    for (int mf = 0; mf < 4; ++mf) {
        const int r_lo = wm * 64 + mf * 16 + grp;
        float s_lo = 0.f, s_hi = 0.f;
#pragma unroll
        for (int nf = 0; nf < 8; ++nf) {
            const int col = wn * 64 + nf * 8 + tg * 2;
            s_lo += v_s[col]     * tanh_fast(c[mf][nf][0] + wq_s[col]);
            s_lo += v_s[col + 1] * tanh_fast(c[mf][nf][1] + wq_s[col + 1]);
            s_hi += v_s[col]     * tanh_fast(c[mf][nf][2] + wq_s[col]);
            s_hi += v_s[col + 1] * tanh_fast(c[mf][nf][3] + wq_s[col + 1]);
        }
        s_lo += __shfl_xor_sync(0xffffffffu, s_lo, 1);
        s_lo += __shfl_xor_sync(0xffffffffu, s_lo, 2);
        s_hi += __shfl_xor_sync(0xffffffffu, s_hi, 1);
        s_hi += __shfl_xor_sync(0xffffffffu, s_hi, 2);
        if (tg == 0) {
            red[wn * 128 + r_lo]     = s_lo;
            red[wn * 128 + r_lo + 8] = s_hi;
        }
    }
    __syncthreads();
    {
        const float s = red[tid] + red[128 + tid];
        g_scores_p[(size_t)ntile * (B_ * S_) + m0 + tid] = s;
    }
}

// ---------------------------------------------------------------------------
// K3: softmax
// ---------------------------------------------------------------------------
__global__ void softmax_kernel(const int* __restrict__ mask,
                               const float* __restrict__ vb,
                               float* __restrict__ attn_out)
{
    const int b = blockIdx.x;
    const int s = threadIdx.x;
    float sc = vb[0];
#pragma unroll
    for (int p = 0; p < 4; ++p) sc += g_scores_p[(size_t)p * (B_ * S_) + b * S_ + s];
    if (mask[b * S_ + s] != 0) sc = -INFINITY;

    __shared__ float red[512];
    red[s] = sc;
    __syncthreads();
    for (int off = 256; off > 0; off >>= 1) {
        if (s < off) red[s] = fmaxf(red[s], red[s + off]);
        __syncthreads();
    }
    const float mx = red[0];
    __syncthreads();
    const float e = expf(sc - mx);
    red[s] = e;
    __syncthreads();
    for (int off = 256; off > 0; off >>= 1) {
        if (s < off) red[s] = red[s] + red[s + off];
        __syncthreads();
    }
    attn_out[b * S_ + s] = e / red[0];
}

// ---------------------------------------------------------------------------
// K4: ctx[b,d] = sum_s attn[b,s] * enc[b,s,d]; epilogue also emits tf32 to
// g_gaf cols 512..1023 (the ctx slice of the gates A operand).
// ---------------------------------------------------------------------------
__global__ void ctx_kernel(const float* __restrict__ enc,
                           const float* __restrict__ attn)
{
    const int b = blockIdx.y;
    const int slice = blockIdx.x;
    const int tid = threadIdx.x;
    const int lane = tid & 31, grp = tid >> 5;

    __shared__ float a_s[S_];
    __shared__ float4 part[256];
    for (int i = tid; i < S_; i += 256) a_s[i] = attn[b * S_ + i];
    __syncthreads();

    const float* base = enc + (size_t)b * S_ * D_ + (size_t)(grp * 64) * D_
                        + slice * 128 + lane * 4;
    const float* aw = a_s + grp * 64;
    float4 acc = make_float4(0.f, 0.f, 0.f, 0.f);
#pragma unroll 8
    for (int s = 0; s < 64; ++s) {
        const float w = aw[s];
        float4 v = *(const float4*)(base + (size_t)s * D_);
        acc.x += w * v.x; acc.y += w * v.y; acc.z += w * v.z; acc.w += w * v.w;
    }
    part[tid] = acc;
    __syncthreads();
    if (tid < 32) {
        float4 t = part[tid];
#pragma unroll
        for (int g = 1; g < 8; ++g) {
            float4 q = part[g * 32 + tid];
            t.x += q.x; t.y += q.y; t.z += q.z; t.w += q.w;
        }
        *(float4*)(g_ctx + b * D_ + slice * 128 + tid * 4) = t;
        uint4 u;
        u.x = tf32b(t.x); u.y = tf32b(t.y); u.z = tf32b(t.z); u.w = tf32b(t.w);
        *(uint4*)(g_gaf + (size_t)b * 1536 + 512 + slice * 128 + tid * 4) = u;
    }
}

// ---------------------------------------------------------------------------
// K5 (TF32 MMA): gates partial GEMM. grid(16, 6). (unchanged)
// ---------------------------------------------------------------------------
__global__ __launch_bounds__(256, 2)
void gates_hmma_kernel(const float* __restrict__ W_ih,
                       const float* __restrict__ W_hh)
{
    extern __shared__ char smem[];
    const int tid = threadIdx.x;
    const int lane = tid & 31, warp = tid >> 5;
    const int wm = warp >> 2, wn = warp & 3;
    const int grp = lane >> 2, tg = lane & 3;
    const int n0 = blockIdx.x * 128;
    const int kbase = blockIdx.y * 256;

    float c[4][4][4];
#pragma unroll
    for (int i = 0; i < 4; ++i)
#pragma unroll
        for (int j = 0; j < 4; ++j)
#pragma unroll
            for (int e = 0; e < 4; ++e) c[i][j][e] = 0.f;

    const uint32_t* As = (const uint32_t*)(smem + T_A);
    const uint32_t* Bs = (const uint32_t*)(smem + T_B);
    const int ld_row = tid >> 4, ld_f4 = tid & 15;

    for (int chunk = 0; chunk < 4; ++chunk) {
        const int k0 = kbase + chunk * 64;
        __syncthreads();
#pragma unroll
        for (int i = 0; i < 8; ++i) {                   // A: tf32 copy
            const int row = ld_row + 16 * i;
            uint4 u = *(const uint4*)(g_gaf + (size_t)row * 1536 + k0 + ld_f4 * 4);
            *(uint4*)(smem + T_A + row * (PAD_F * 4) + ld_f4 * 16) = u;
        }
        if (k0 < 1024) {
#pragma unroll
            for (int i = 0; i < 8; ++i) {
                const int row = ld_row + 16 * i;
                float4 v = *(const float4*)(W_ih + (size_t)(n0 + row) * 1024 + k0 + ld_f4 * 4);
                cvt_store4(v, smem + T_B, row, ld_f4);
            }
        } else {
#pragma unroll
            for (int i = 0; i < 8; ++i) {
                const int row = ld_row + 16 * i;
                float4 v = *(const float4*)(W_hh + (size_t)(n0 + row) * 512 + (k0 - 1024) + ld_f4 * 4);
                cvt_store4(v, smem + T_B, row, ld_f4);
            }
        }
        __syncthreads();

#pragma unroll
        for (int ks = 0; ks < 8; ++ks) {
            uint32_t a[4][4];
#pragma unroll
            for (int mf = 0; mf < 4; ++mf) {
                const uint32_t* p = As + (wm * 64 + mf * 16 + grp) * PAD_F + ks * 8 + tg;
                a[mf][0] = p[0]; a[mf][1] = p[8 * PAD_F];
                a[mf][2] = p[4]; a[mf][3] = p[8 * PAD_F + 4];
            }
            uint32_t bf[4][2];
#pragma unroll
            for (int nf = 0; nf < 4; ++nf) {
                const uint32_t* q = Bs + (wn * 32 + nf * 8 + grp) * PAD_F + ks * 8 + tg;
                bf[nf][0] = q[0]; bf[nf][1] = q[4];
            }
#pragma unroll
            for (int mf = 0; mf < 4; ++mf)
#pragma unroll
                for (int nf = 0; nf < 4; ++nf)
                    mma_tf32(c[mf][nf], a[mf], bf[nf][0], bf[nf][1]);
        }
    }

    float* dst = g_gates_p + (size_t)blockIdx.y * (B_ * 4 * H_);
#pragma unroll
    for (int mf = 0; mf < 4; ++mf) {
        const int r0 = wm * 64 + mf * 16 + grp;
#pragma unroll
        for (int nf = 0; nf < 4; ++nf) {
            const int col = n0 + wn * 32 + nf * 8 + tg * 2;
            dst[(size_t)r0 * 2048 + col]           = c[mf][nf][0];
            dst[(size_t)r0 * 2048 + col + 1]       = c[mf][nf][1];
            dst[(size_t)(r0 + 8) * 2048 + col]     = c[mf][nf][2];
            dst[(size_t)(r0 + 8) * 2048 + col + 1] = c[mf][nf][3];
        }
    }
}

// ---------------------------------------------------------------------------
// K6: LSTM elementwise (emits hidden tf32 bits)
// ---------------------------------------------------------------------------
__device__ __forceinline__ float sigm(float x) { return 1.f / (1.f + expf(-x)); }

__global__ void lstm_kernel(const float* __restrict__ c0,
                            const float* __restrict__ b_ih,
                            const float* __restrict__ b_hh,
                            float* __restrict__ out_hidden,
                            float* __restrict__ out_cell)
{
    const int i = blockIdx.x * blockDim.x + threadIdx.x;
    const int b = i >> 9;
    const int h = i & 511;
    float ig = b_ih[h]        + b_hh[h];
    float fg = b_ih[512 + h]  + b_hh[512 + h];
    float gg = b_ih[1024 + h] + b_hh[1024 + h];
    float og = b_ih[1536 + h] + b_hh[1536 + h];
#pragma unroll
    for (int p = 0; p < 6; ++p) {
        const float* gp = g_gates_p + (size_t)p * (B_ * 4 * H_) + (size_t)b * 2048;
        ig += gp[h]; fg += gp[512 + h]; gg += gp[1024 + h]; og += gp[1536 + h];
    }
    const float cell = sigm(fg) * c0[i] + sigm(ig) * tanhf(gg);
    const float hid  = sigm(og) * tanhf(cell);
    out_cell[i]   = cell;
    out_hidden[i] = hid;
    g_hf[i] = tf32b(hid);
}

// ---------------------------------------------------------------------------
// K7 (TF32 MMA): logits = hidden @ ent_W^T + ent_b. (round-13 config)
// 128 threads = 4 warps (2x2), warp tile 64x64.
// ---------------------------------------------------------------------------
#define LG_EB  T2_END
#define LG_SZ  (T2_END + 512)

__global__ __launch_bounds__(128, 2)
void logits_hmma_kernel(const float* __restrict__ entW,
                        const float* __restrict__ entb,
                        float* __restrict__ out)
{
    extern __shared__ char smem[];
    const int tid = threadIdx.x;
    const int lane = tid & 31, warp = tid >> 5;
    const int wm = warp >> 1, wn = warp & 1;
    const int grp = lane >> 2, tg = lane & 3;
    const int n0 = blockIdx.x * 128;

    float* eb = (float*)(smem + LG_EB);
    {
        const int v = n0 + tid;
        eb[tid] = (v < V_) ? entb[v] : 0.f;
    }

    float c[4][8][4];
#pragma unroll
    for (int i = 0; i < 4; ++i)
#pragma unroll
        for (int j = 0; j < 8; ++j)
#pragma unroll
            for (int e = 0; e < 4; ++e) c[i][j][e] = 0.f;

    const uint32_t* As = (const uint32_t*)(smem + T_A);
    const uint32_t* Bs = (const uint32_t*)(smem + T_B);
    const int ld_row = tid >> 4, ld_f4 = tid & 15;

    for (int chunk = 0; chunk < 8; ++chunk) {
        const int k0 = chunk * 64;
        __syncthreads();
#pragma unroll
        for (int i = 0; i < 16; ++i) {                // A: hidden tf32 copy
            const int row = ld_row + 8 * i;
            uint4 u = *(const uint4*)(g_hf + (size_t)row * H_ + k0 + ld_f4 * 4);
            *(uint4*)(smem + T_A + row * (PAD_F * 4) + ld_f4 * 16) = u;
        }
#pragma unroll
        for (int i = 0; i < 16; ++i) {                // B: ent_W fp32 (guarded)
            const int row = ld_row + 8 * i;
            float4 v = make_float4(0.f, 0.f, 0.f, 0.f);
            if (n0 + row < V_)
                v = *(const float4*)(entW + (size_t)(n0 + row) * H_ + k0 + ld_f4 * 4);
            cvt_store4(v, smem + T_B, row, ld_f4);
        }
        __syncthreads();

#pragma unroll
        for (int ks = 0; ks < 8; ++ks) {
            uint32_t a[4][4];
#pragma unroll
            for (int mf = 0; mf < 4; ++mf) {
                const uint32_t* p = As + (wm * 64 + mf * 16 + grp) * PAD_F + ks * 8 + tg;
                a[mf][0] = p[0]; a[mf][1] = p[8 * PAD_F];
                a[mf][2] = p[4]; a[mf][3] = p[8 * PAD_F + 4];
            }
            uint32_t bf[8][2];
#pragma unroll
            for (int nf = 0; nf < 8; ++nf) {
                const uint32_t* q = Bs + (wn * 64 + nf * 8 + grp) * PAD_F + ks * 8 + tg;
                bf[nf][0] = q[0]; bf[nf][1] = q[4];
            }
#pragma unroll
            for (int mf = 0; mf < 4; ++mf)
#pragma unroll
                for (int nf = 0; nf < 8; ++nf)
                    mma_tf32(c[mf][nf], a[mf], bf[nf][0], bf[nf][1]);
        }
    }

    __syncthreads();
    float* stage = (float*)smem;                        // [128][132]
#pragma unroll
    for (int mf = 0; mf < 4; ++mf) {
        const int r_lo = wm * 64 + mf * 16 + grp;
#pragma unroll
        for (int nf = 0; nf < 8; ++nf) {
            const int col = wn * 64 + nf * 8 + tg * 2;
            stage[r_lo * 132 + col]           = c[mf][nf][0] + eb[col];
            stage[r_lo * 132 + col + 1]       = c[mf][nf][1] + eb[col + 1];
            stage[(r_lo + 8) * 132 + col]     = c[mf][nf][2] + eb[col];
            stage[(r_lo + 8) * 132 + col + 1] = c[mf][nf][3] + eb[col + 1];
        }
    }
    __syncthreads();

    {
        const int col4 = lane * 4;
        const int v0 = n0 + col4;
#pragma unroll
        for (int i = 0; i < 32; ++i) {
            const int r = i * 4 + warp;
            if (v0 + 3 < V_) {
                *(float4*)(out + (size_t)r * V_ + v0) = *(float4*)(stage + r * 132 + col4);
            } else {
#pragma unroll
                for (int e = 0; e < 4; ++e)
                    if (v0 + e < V_)
                        out[(size_t)r * V_ + v0 + e] = stage[r * 132 + col4 + e];
            }
        }
    }
}

// ---------------------------------------------------------------------------
extern "C" void kernel_launch(void* const* d_in, const int* in_sizes, int n_in,
                              void* d_out, int out_size)
{
    (void)in_sizes; (void)n_in; (void)out_size;

    const float* y_prev  = (const float*)d_in[0];
    const float* h0      = (const float*)d_in[1];
    const float* c0      = (const float*)d_in[2];
    const float* enc_hs  = (const float*)d_in[3];
    const int*   src_mask = (const int*)d_in[5];
    const float* W_ctx   = (const float*)d_in[6];
    const float* W_q     = (const float*)d_in[7];
    const float* b_q     = (const float*)d_in[8];
    const float* v_w     = (const float*)d_in[9];
    const float* v_b     = (const float*)d_in[10];
    const float* W_ih    = (const float*)d_in[11];
    const float* W_hh    = (const float*)d_in[12];
    const float* b_ih    = (const float*)d_in[13];
    const float* b_hh    = (const float*)d_in[14];
    const float* ent_W   = (const float*)d_in[15];
    const float* ent_b   = (const float*)d_in[16];

    float* out        = (float*)d_out;
    float* out_logits = out;
    float* out_hidden = out + OUT_HID;
    float* out_cell   = out + OUT_CELL;
    float* out_attn   = out + OUT_ATTN;

    cudaFuncSetAttribute(attn_hmma_kernel, cudaFuncAttributeMaxDynamicSharedMemorySize, AT_SZ);
    cudaFuncSetAttribute(gates_hmma_kernel, cudaFuncAttributeMaxDynamicSharedMemorySize, T2_END);
    cudaFuncSetAttribute(logits_hmma_kernel, cudaFuncAttributeMaxDynamicSharedMemorySize, LG_SZ);

    wc_prep_kernel<<<192, 256>>>(W_ctx, 0, y_prev, 0);        // launch 0 (+y_prev prep)
    wc_prep_kernel<<<192, 256>>>(W_ctx, 32768, h0, 1024);     // launch 1 (+h0 prep)
    wq_kernel<<<16, 512>>>(h0, W_q, b_q);                     // launch 2
    attn_hmma_kernel<<<dim3(4, (B_ * S_) / 128), 128, AT_SZ>>>(enc_hs, v_w);  // launch 3 (profiled)
    softmax_kernel<<<B_, S_>>>(src_mask, v_b, out_attn);
    ctx_kernel<<<dim3(4, B_), 256>>>(enc_hs, out_attn);
    gates_hmma_kernel<<<dim3(16, 6), 256, T2_END>>>(W_ih, W_hh);
    lstm_kernel<<<(B_ * H_) / 256, 256>>>(c0, b_ih, b_hh, out_hidden, out_cell);
    logits_hmma_kernel<<<(V_ + 127) / 128, 128, LG_SZ>>>(ent_W, ent_b, out_logits);
}

// round 15
// speedup vs baseline: 1.6332x; 1.6332x over previous
#include <cuda_runtime.h>
#include <cuda_bf16.h>
#include <math.h>
#include <stdint.h>

// Problem constants
#define B_ 128
#define S_ 512
#define D_ 512
#define H_ 512
#define V_ 50000

// d_out layout: logits | hidden | cell | attn
#define OUT_HID  (B_ * V_)
#define OUT_CELL (OUT_HID + B_ * H_)
#define OUT_ATTN (OUT_CELL + B_ * H_)

// ---------------- device scratch ----------------
__device__ float g_wq[B_ * D_];
__device__ float g_ctx[B_ * D_];
__device__ float g_scores_p[4 * B_ * S_];
__device__ float g_gates_p[6 * B_ * 4 * H_];
__device__ uint32_t g_wcf[D_ * D_];        // W_ctx as tf32 bits
__device__ uint32_t g_gaf[B_ * 1536];      // concat(y_prev,ctx,h0) tf32 bits
__device__ uint32_t g_hf[B_ * H_];         // hidden tf32 bits

// ======================= helpers =======================
__device__ __forceinline__ uint32_t tf32b(float x) {
    uint32_t r;
    asm("cvt.rna.tf32.f32 %0, %1;" : "=r"(r) : "f"(x));
    return r;
}

__device__ __forceinline__ void mma_tf32(float* d, const uint32_t* a,
                                         uint32_t b0, uint32_t b1) {
    asm volatile("mma.sync.aligned.m16n8k8.row.col.f32.tf32.tf32.f32 "
        "{%0,%1,%2,%3},{%4,%5,%6,%7},{%8,%9},{%0,%1,%2,%3};"
        : "+f"(d[0]), "+f"(d[1]), "+f"(d[2]), "+f"(d[3])
        : "r"(a[0]), "r"(a[1]), "r"(a[2]), "r"(a[3]), "r"(b0), "r"(b1));
}

__device__ __forceinline__ float tanh_fast(float x) {
    float y;
    asm("tanh.approx.f32 %0, %1;" : "=f"(y) : "f"(x));
    return y;
}

// tf32 tile: 64 k-words + 4 pad = 68 words (272 B) per row, 128 rows
#define PAD_F 68
#define T_A   0
#define T_B   34816
#define T2_END 69632

__device__ __forceinline__ void cvt_store4(float4 v, char* base, int row, int f4) {
    uint4 u;
    u.x = tf32b(v.x); u.y = tf32b(v.y); u.z = tf32b(v.z); u.w = tf32b(v.w);
    *(uint4*)(base + row * (PAD_F * 4) + f4 * 16) = u;
}

// ---------------------------------------------------------------------------
// K0a/K0b: pre-convert W_ctx to tf32 (blocks 0-127) + one gates operand
// (blocks 128-191: launch 0 -> y_prev at col 0; launch 1 -> h0 at col 1024)
// ---------------------------------------------------------------------------
__global__ void wc_prep_kernel(const float* __restrict__ Wc, int base,
                               const float* __restrict__ extra, int coloff)
{
    if (blockIdx.x < 128) {
        const int i = base + blockIdx.x * 256 + threadIdx.x;
        float4 v = ((const float4*)Wc)[i];
        uint4 u;
        u.x = tf32b(v.x); u.y = tf32b(v.y); u.z = tf32b(v.z); u.w = tf32b(v.w);
        ((uint4*)g_wcf)[i] = u;
    } else {
        const int j = (blockIdx.x - 128) * 256 + threadIdx.x;  // 0..16383 f4s
        const int row = j >> 7, c4 = j & 127;
        float4 v = ((const float4*)(extra + (size_t)row * 512))[c4];
        uint4 u;
        u.x = tf32b(v.x); u.y = tf32b(v.y); u.z = tf32b(v.z); u.w = tf32b(v.w);
        *(uint4*)(g_gaf + (size_t)row * 1536 + coloff + c4 * 4) = u;
    }
}

// ---------------------------------------------------------------------------
// K1: wq = h0 @ W_q^T + b_q.
// grid (8 dslices, 32 bgroups) = 256 blocks (>=148: avoids low-grid SM
// throttle that poisoned round 14). Block: 64 d-cols x 4 batch rows,
// k split 4-way across thread groups + smem reduce.
// W_q traffic = 32 x 1MB = 32 MB (vs 128 MB at 1 row/block).
// ---------------------------------------------------------------------------
__global__ __launch_bounds__(256)
void wq_kernel(const float* __restrict__ h0,
               const float* __restrict__ Wq,
               const float* __restrict__ bq)
{
    const int dbase = blockIdx.x * 64;
    const int b0 = blockIdx.y * 4;
    const int tid = threadIdx.x;
    const int col = tid & 63;       // 0..63
    const int seg = tid >> 6;       // 0..3, 128 k each

    __shared__ float hs[4][512];
    __shared__ float part[4][64][4];
    for (int i = tid; i < 2048; i += 256) hs[i >> 9][i & 511] = h0[b0 * 512 + i];
    __syncthreads();

    const int d = dbase + col;
    const float4* w = (const float4*)(Wq + (size_t)d * 512 + seg * 128);
    float acc[4] = {0.f, 0.f, 0.f, 0.f};
#pragma unroll 8
    for (int k4 = 0; k4 < 32; ++k4) {
        const float4 wv = w[k4];
#pragma unroll
        for (int r = 0; r < 4; ++r) {
            const float4 hv = ((const float4*)(hs[r] + seg * 128))[k4];
            acc[r] += wv.x * hv.x + wv.y * hv.y + wv.z * hv.z + wv.w * hv.w;
        }
    }
#pragma unroll
    for (int r = 0; r < 4; ++r) part[seg][col][r] = acc[r];
    __syncthreads();
    if (seg == 0) {
        const float bqd = bq[d];
#pragma unroll
        for (int r = 0; r < 4; ++r) {
            const float s = part[0][col][r] + part[1][col][r]
                          + part[2][col][r] + part[3][col][r];
            g_wq[(size_t)(b0 + r) * D_ + d] = s + bqd;
        }
    }
}

// ---------------------------------------------------------------------------
// K2 (TF32 MMA): fused attention-score GEMM. (round-13 best config)
// ---------------------------------------------------------------------------
#define AT_RED  T2_END                 // float[2][128]
#define AT_WQ   (AT_RED + 1024)
#define AT_V    (AT_WQ + 512)
#define AT_SZ   (AT_V + 512)           // 71680

__global__ __launch_bounds__(128, 2)
void attn_hmma_kernel(const float* __restrict__ enc,
                      const float* __restrict__ vw)
{
    extern __shared__ char smem[];
    const int tid = threadIdx.x;
    const int lane = tid & 31, warp = tid >> 5;
    const int wm = warp >> 1, wn = warp & 1;
    const int grp = lane >> 2, tg = lane & 3;
    const int ntile = blockIdx.x;
    const int m0 = blockIdx.y * 128;
    const int n0 = ntile * 128;
    const int b = m0 >> 9;

    float* wq_s = (float*)(smem + AT_WQ);
    float* v_s  = (float*)(smem + AT_V);
    wq_s[tid] = g_wq[b * D_ + n0 + tid];
    v_s[tid]  = vw[n0 + tid];

    float c[4][8][4];
#pragma unroll
    for (int i = 0; i < 4; ++i)
#pragma unroll
        for (int j = 0; j < 8; ++j)
#pragma unroll
            for (int e = 0; e < 4; ++e) c[i][j][e] = 0.f;

    const uint32_t* As = (const uint32_t*)(smem + T_A);
    const uint32_t* Bs = (const uint32_t*)(smem + T_B);
    const int ld_row = tid >> 4, ld_f4 = tid & 15;

    for (int chunk = 0; chunk < 8; ++chunk) {
        const int k0 = chunk * 64;
        __syncthreads();
#pragma unroll
        for (int i = 0; i < 16; ++i) {                // A: enc fp32 -> tf32
            const int row = ld_row + 8 * i;
            float4 v = *(const float4*)(enc + (size_t)(m0 + row) * D_ + k0 + ld_f4 * 4);
            cvt_store4(v, smem + T_A, row, ld_f4);
        }
#pragma unroll
        for (int i = 0; i < 16; ++i) {                // B: tf32 copy
            const int row = ld_row + 8 * i;
            uint4 u = *(const uint4*)(g_wcf + (size_t)(n0 + row) * D_ + k0 + ld_f4 * 4);
            *(uint4*)(smem + T_B + row * (PAD_F * 4) + ld_f4 * 16) = u;
        }
        __syncthreads();

#pragma unroll
        for (int ks = 0; ks < 8; ++ks) {
            uint32_t a[4][4];
#pragma unroll
            for (int mf = 0; mf < 4; ++mf) {
                const uint32_t* p = As + (wm * 64 + mf * 16 + grp) * PAD_F + ks * 8 + tg;
                a[mf][0] = p[0]; a[mf][1] = p[8 * PAD_F];
                a[mf][2] = p[4]; a[mf][3] = p[8 * PAD_F + 4];
            }
            uint32_t bf[8][2];
#pragma unroll
            for (int nf = 0; nf < 8; ++nf) {
                const uint32_t* q = Bs + (wn * 64 + nf * 8 + grp) * PAD_F + ks * 8 + tg;
                bf[nf][0] = q[0]; bf[nf][1] = q[4];
            }
#pragma unroll
            for (int mf = 0; mf < 4; ++mf)
#pragma unroll
                for (int nf = 0; nf < 8; ++nf)
                    mma_tf32(c[mf][nf], a[mf], bf[nf][0], bf[nf][1]);
        }
    }

    float* red = (float*)(smem + AT_RED);             // [2][128]
    __syncthreads();
#pragma unroll
    for (int mf = 0; mf < 4; ++mf) {
        const int r_lo = wm * 64 + mf * 16 + grp;
        float s_lo = 0.f, s_hi = 0.f;
#pragma unroll
        for (int nf = 0; nf < 8; ++nf) {
            const int col = wn * 64 + nf * 8 + tg * 2;
            s_lo += v_s[col]     * tanh_fast(c[mf][nf][0] + wq_s[col]);
            s_lo += v_s[col + 1] * tanh_fast(c[mf][nf][1] + wq_s[col + 1]);
            s_hi += v_s[col]     * tanh_fast(c[mf][nf][2] + wq_s[col]);
            s_hi += v_s[col + 1] * tanh_fast(c[mf][nf][3] + wq_s[col + 1]);
        }
        s_lo += __shfl_xor_sync(0xffffffffu, s_lo, 1);
        s_lo += __shfl_xor_sync(0xffffffffu, s_lo, 2);
        s_hi += __shfl_xor_sync(0xffffffffu, s_hi, 1);
        s_hi += __shfl_xor_sync(0xffffffffu, s_hi, 2);
        if (tg == 0) {
            red[wn * 128 + r_lo]     = s_lo;
            red[wn * 128 + r_lo + 8] = s_hi;
        }
    }
    __syncthreads();
    {
        const float s = red[tid] + red[128 + tid];
        g_scores_p[(size_t)ntile * (B_ * S_) + m0 + tid] = s;
    }
}

// ---------------------------------------------------------------------------
// K3: softmax
// ---------------------------------------------------------------------------
__global__ void softmax_kernel(const int* __restrict__ mask,
                               const float* __restrict__ vb,
                               float* __restrict__ attn_out)
{
    const int b = blockIdx.x;
    const int s = threadIdx.x;
    float sc = vb[0];
#pragma unroll
    for (int p = 0; p < 4; ++p) sc += g_scores_p[(size_t)p * (B_ * S_) + b * S_ + s];
    if (mask[b * S_ + s] != 0) sc = -INFINITY;

    __shared__ float red[512];
    red[s] = sc;
    __syncthreads();
    for (int off = 256; off > 0; off >>= 1) {
        if (s < off) red[s] = fmaxf(red[s], red[s + off]);
        __syncthreads();
    }
    const float mx = red[0];
    __syncthreads();
    const float e = expf(sc - mx);
    red[s] = e;
    __syncthreads();
    for (int off = 256; off > 0; off >>= 1) {
        if (s < off) red[s] = red[s] + red[s + off];
        __syncthreads();
    }
    attn_out[b * S_ + s] = e / red[0];
}

// ---------------------------------------------------------------------------
// K4: ctx[b,d] = sum_s attn[b,s] * enc[b,s,d]; epilogue also emits tf32 to
// g_gaf cols 512..1023 (the ctx slice of the gates A operand).
// ---------------------------------------------------------------------------
__global__ void ctx_kernel(const float* __restrict__ enc,
                           const float* __restrict__ attn)
{
    const int b = blockIdx.y;
    const int slice = blockIdx.x;
    const int tid = threadIdx.x;
    const int lane = tid & 31, grp = tid >> 5;

    __shared__ float a_s[S_];
    __shared__ float4 part[256];
    for (int i = tid; i < S_; i += 256) a_s[i] = attn[b * S_ + i];
    __syncthreads();

    const float* base = enc + (size_t)b * S_ * D_ + (size_t)(grp * 64) * D_
                        + slice * 128 + lane * 4;
    const float* aw = a_s + grp * 64;
    float4 acc = make_float4(0.f, 0.f, 0.f, 0.f);
#pragma unroll 8
    for (int s = 0; s < 64; ++s) {
        const float w = aw[s];
        float4 v = *(const float4*)(base + (size_t)s * D_);
        acc.x += w * v.x; acc.y += w * v.y; acc.z += w * v.z; acc.w += w * v.w;
    }
    part[tid] = acc;
    __syncthreads();
    if (tid < 32) {
        float4 t = part[tid];
#pragma unroll
        for (int g = 1; g < 8; ++g) {
            float4 q = part[g * 32 + tid];
            t.x += q.x; t.y += q.y; t.z += q.z; t.w += q.w;
        }
        *(float4*)(g_ctx + b * D_ + slice * 128 + tid * 4) = t;
        uint4 u;
        u.x = tf32b(t.x); u.y = tf32b(t.y); u.z = tf32b(t.z); u.w = tf32b(t.w);
        *(uint4*)(g_gaf + (size_t)b * 1536 + 512 + slice * 128 + tid * 4) = u;
    }
}

// ---------------------------------------------------------------------------
// K5 (TF32 MMA): gates partial GEMM. grid(16, 6). (unchanged)
// ---------------------------------------------------------------------------
__global__ __launch_bounds__(256, 2)
void gates_hmma_kernel(const float* __restrict__ W_ih,
                       const float* __restrict__ W_hh)
{
    extern __shared__ char smem[];
    const int tid = threadIdx.x;
    const int lane = tid & 31, warp = tid >> 5;
    const int wm = warp >> 2, wn = warp & 3;
    const int grp = lane >> 2, tg = lane & 3;
    const int n0 = blockIdx.x * 128;
    const int kbase = blockIdx.y * 256;

    float c[4][4][4];
#pragma unroll
    for (int i = 0; i < 4; ++i)
#pragma unroll
        for (int j = 0; j < 4; ++j)
#pragma unroll
            for (int e = 0; e < 4; ++e) c[i][j][e] = 0.f;

    const uint32_t* As = (const uint32_t*)(smem + T_A);
    const uint32_t* Bs = (const uint32_t*)(smem + T_B);
    const int ld_row = tid >> 4, ld_f4 = tid & 15;

    for (int chunk = 0; chunk < 4; ++chunk) {
        const int k0 = kbase + chunk * 64;
        __syncthreads();
#pragma unroll
        for (int i = 0; i < 8; ++i) {                   // A: tf32 copy
            const int row = ld_row + 16 * i;
            uint4 u = *(const uint4*)(g_gaf + (size_t)row * 1536 + k0 + ld_f4 * 4);
            *(uint4*)(smem + T_A + row * (PAD_F * 4) + ld_f4 * 16) = u;
        }
        if (k0 < 1024) {
#pragma unroll
            for (int i = 0; i < 8; ++i) {
                const int row = ld_row + 16 * i;
                float4 v = *(const float4*)(W_ih + (size_t)(n0 + row) * 1024 + k0 + ld_f4 * 4);
                cvt_store4(v, smem + T_B, row, ld_f4);
            }
        } else {
#pragma unroll
            for (int i = 0; i < 8; ++i) {
                const int row = ld_row + 16 * i;
                float4 v = *(const float4*)(W_hh + (size_t)(n0 + row) * 512 + (k0 - 1024) + ld_f4 * 4);
                cvt_store4(v, smem + T_B, row, ld_f4);
            }
        }
        __syncthreads();

#pragma unroll
        for (int ks = 0; ks < 8; ++ks) {
            uint32_t a[4][4];
#pragma unroll
            for (int mf = 0; mf < 4; ++mf) {
                const uint32_t* p = As + (wm * 64 + mf * 16 + grp) * PAD_F + ks * 8 + tg;
                a[mf][0] = p[0]; a[mf][1] = p[8 * PAD_F];
                a[mf][2] = p[4]; a[mf][3] = p[8 * PAD_F + 4];
            }
            uint32_t bf[4][2];
#pragma unroll
            for (int nf = 0; nf < 4; ++nf) {
                const uint32_t* q = Bs + (wn * 32 + nf * 8 + grp) * PAD_F + ks * 8 + tg;
                bf[nf][0] = q[0]; bf[nf][1] = q[4];
            }
#pragma unroll
            for (int mf = 0; mf < 4; ++mf)
#pragma unroll
                for (int nf = 0; nf < 4; ++nf)
                    mma_tf32(c[mf][nf], a[mf], bf[nf][0], bf[nf][1]);
        }
    }

    float* dst = g_gates_p + (size_t)blockIdx.y * (B_ * 4 * H_);
#pragma unroll
    for (int mf = 0; mf < 4; ++mf) {
        const int r0 = wm * 64 + mf * 16 + grp;
#pragma unroll
        for (int nf = 0; nf < 4; ++nf) {
            const int col = n0 + wn * 32 + nf * 8 + tg * 2;
            dst[(size_t)r0 * 2048 + col]           = c[mf][nf][0];
            dst[(size_t)r0 * 2048 + col + 1]       = c[mf][nf][1];
            dst[(size_t)(r0 + 8) * 2048 + col]     = c[mf][nf][2];
            dst[(size_t)(r0 + 8) * 2048 + col + 1] = c[mf][nf][3];
        }
    }
}

// ---------------------------------------------------------------------------
// K6: LSTM elementwise (emits hidden tf32 bits)
// ---------------------------------------------------------------------------
__device__ __forceinline__ float sigm(float x) { return 1.f / (1.f + expf(-x)); }

__global__ void lstm_kernel(const float* __restrict__ c0,
                            const float* __restrict__ b_ih,
                            const float* __restrict__ b_hh,
                            float* __restrict__ out_hidden,
                            float* __restrict__ out_cell)
{
    const int i = blockIdx.x * blockDim.x + threadIdx.x;
    const int b = i >> 9;
    const int h = i & 511;
    float ig = b_ih[h]        + b_hh[h];
    float fg = b_ih[512 + h]  + b_hh[512 + h];
    float gg = b_ih[1024 + h] + b_hh[1024 + h];
    float og = b_ih[1536 + h] + b_hh[1536 + h];
#pragma unroll
    for (int p = 0; p < 6; ++p) {
        const float* gp = g_gates_p + (size_t)p * (B_ * 4 * H_) + (size_t)b * 2048;
        ig += gp[h]; fg += gp[512 + h]; gg += gp[1024 + h]; og += gp[1536 + h];
    }
    const float cell = sigm(fg) * c0[i] + sigm(ig) * tanhf(gg);
    const float hid  = sigm(og) * tanhf(cell);
    out_cell[i]   = cell;
    out_hidden[i] = hid;
    g_hf[i] = tf32b(hid);
}

// ---------------------------------------------------------------------------
// K7 (TF32 MMA): logits = hidden @ ent_W^T + ent_b. (round-13 config)
// 128 threads = 4 warps (2x2), warp tile 64x64.
// ---------------------------------------------------------------------------
#define LG_EB  T2_END
#define LG_SZ  (T2_END + 512)

__global__ __launch_bounds__(128, 2)
void logits_hmma_kernel(const float* __restrict__ entW,
                        const float* __restrict__ entb,
                        float* __restrict__ out)
{
    extern __shared__ char smem[];
    const int tid = threadIdx.x;
    const int lane = tid & 31, warp = tid >> 5;
    const int wm = warp >> 1, wn = warp & 1;
    const int grp = lane >> 2, tg = lane & 3;
    const int n0 = blockIdx.x * 128;

    float* eb = (float*)(smem + LG_EB);
    {
        const int v = n0 + tid;
        eb[tid] = (v < V_) ? entb[v] : 0.f;
    }

    float c[4][8][4];
#pragma unroll
    for (int i = 0; i < 4; ++i)
#pragma unroll
        for (int j = 0; j < 8; ++j)
#pragma unroll
            for (int e = 0; e < 4; ++e) c[i][j][e] = 0.f;

    const uint32_t* As = (const uint32_t*)(smem + T_A);
    const uint32_t* Bs = (const uint32_t*)(smem + T_B);
    const int ld_row = tid >> 4, ld_f4 = tid & 15;

    for (int chunk = 0; chunk < 8; ++chunk) {
        const int k0 = chunk * 64;
        __syncthreads();
#pragma unroll
        for (int i = 0; i < 16; ++i) {                // A: hidden tf32 copy
            const int row = ld_row + 8 * i;
            uint4 u = *(const uint4*)(g_hf + (size_t)row * H_ + k0 + ld_f4 * 4);
            *(uint4*)(smem + T_A + row * (PAD_F * 4) + ld_f4 * 16) = u;
        }
#pragma unroll
        for (int i = 0; i < 16; ++i) {                // B: ent_W fp32 (guarded)
            const int row = ld_row + 8 * i;
            float4 v = make_float4(0.f, 0.f, 0.f, 0.f);
            if (n0 + row < V_)
                v = *(const float4*)(entW + (size_t)(n0 + row) * H_ + k0 + ld_f4 * 4);
            cvt_store4(v, smem + T_B, row, ld_f4);
        }
        __syncthreads();

#pragma unroll
        for (int ks = 0; ks < 8; ++ks) {
            uint32_t a[4][4];
#pragma unroll
            for (int mf = 0; mf < 4; ++mf) {
                const uint32_t* p = As + (wm * 64 + mf * 16 + grp) * PAD_F + ks * 8 + tg;
                a[mf][0] = p[0]; a[mf][1] = p[8 * PAD_F];
                a[mf][2] = p[4]; a[mf][3] = p[8 * PAD_F + 4];
            }
            uint32_t bf[8][2];
#pragma unroll
            for (int nf = 0; nf < 8; ++nf) {
                const uint32_t* q = Bs + (wn * 64 + nf * 8 + grp) * PAD_F + ks * 8 + tg;
                bf[nf][0] = q[0]; bf[nf][1] = q[4];
            }
#pragma unroll
            for (int mf = 0; mf < 4; ++mf)
#pragma unroll
                for (int nf = 0; nf < 8; ++nf)
                    mma_tf32(c[mf][nf], a[mf], bf[nf][0], bf[nf][1]);
        }
    }

    __syncthreads();
    float* stage = (float*)smem;                        // [128][132]
#pragma unroll
    for (int mf = 0; mf < 4; ++mf) {
        const int r_lo = wm * 64 + mf * 16 + grp;
#pragma unroll
        for (int nf = 0; nf < 8; ++nf) {
            const int col = wn * 64 + nf * 8 + tg * 2;
            stage[r_lo * 132 + col]           = c[mf][nf][0] + eb[col];
            stage[r_lo * 132 + col + 1]       = c[mf][nf][1] + eb[col + 1];
            stage[(r_lo + 8) * 132 + col]     = c[mf][nf][2] + eb[col];
            stage[(r_lo + 8) * 132 + col + 1] = c[mf][nf][3] + eb[col + 1];
        }
    }
    __syncthreads();

    {
        const int col4 = lane * 4;
        const int v0 = n0 + col4;
#pragma unroll
        for (int i = 0; i < 32; ++i) {
            const int r = i * 4 + warp;
            if (v0 + 3 < V_) {
                *(float4*)(out + (size_t)r * V_ + v0) = *(float4*)(stage + r * 132 + col4);
            } else {
#pragma unroll
                for (int e = 0; e < 4; ++e)
                    if (v0 + e < V_)
                        out[(size_t)r * V_ + v0 + e] = stage[r * 132 + col4 + e];
            }
        }
    }
}

// ---------------------------------------------------------------------------
extern "C" void kernel_launch(void* const* d_in, const int* in_sizes, int n_in,
                              void* d_out, int out_size)
{
    (void)in_sizes; (void)n_in; (void)out_size;

    const float* y_prev  = (const float*)d_in[0];
    const float* h0      = (const float*)d_in[1];
    const float* c0      = (const float*)d_in[2];
    const float* enc_hs  = (const float*)d_in[3];
    const int*   src_mask = (const int*)d_in[5];
    const float* W_ctx   = (const float*)d_in[6];
    const float* W_q     = (const float*)d_in[7];
    const float* b_q     = (const float*)d_in[8];
    const float* v_w     = (const float*)d_in[9];
    const float* v_b     = (const float*)d_in[10];
    const float* W_ih    = (const float*)d_in[11];
    const float* W_hh    = (const float*)d_in[12];
    const float* b_ih    = (const float*)d_in[13];
    const float* b_hh    = (const float*)d_in[14];
    const float* ent_W   = (const float*)d_in[15];
    const float* ent_b   = (const float*)d_in[16];

    float* out        = (float*)d_out;
    float* out_logits = out;
    float* out_hidden = out + OUT_HID;
    float* out_cell   = out + OUT_CELL;
    float* out_attn   = out + OUT_ATTN;

    cudaFuncSetAttribute(attn_hmma_kernel, cudaFuncAttributeMaxDynamicSharedMemorySize, AT_SZ);
    cudaFuncSetAttribute(gates_hmma_kernel, cudaFuncAttributeMaxDynamicSharedMemorySize, T2_END);
    cudaFuncSetAttribute(logits_hmma_kernel, cudaFuncAttributeMaxDynamicSharedMemorySize, LG_SZ);

    wc_prep_kernel<<<192, 256>>>(W_ctx, 0, y_prev, 0);        // launch 0 (+y_prev prep)
    wc_prep_kernel<<<192, 256>>>(W_ctx, 32768, h0, 1024);     // launch 1 (+h0 prep)
    wq_kernel<<<dim3(8, 32), 256>>>(h0, W_q, b_q);            // launch 2 (256 blocks)
    attn_hmma_kernel<<<dim3(4, (B_ * S_) / 128), 128, AT_SZ>>>(enc_hs, v_w);  // launch 3 (profiled)
    softmax_kernel<<<B_, S_>>>(src_mask, v_b, out_attn);
    ctx_kernel<<<dim3(4, B_), 256>>>(enc_hs, out_attn);
    gates_hmma_kernel<<<dim3(16, 6), 256, T2_END>>>(W_ih, W_hh);
    lstm_kernel<<<(B_ * H_) / 256, 256>>>(c0, b_ih, b_hh, out_hidden, out_cell);
    logits_hmma_kernel<<<(V_ + 127) / 128, 128, LG_SZ>>>(ent_W, ent_b, out_logits);
}